// round 6
// baseline (speedup 1.0000x reference)
#include <cuda_runtime.h>
#include <cuda_fp16.h>
#include <cstdint>

#define B_  4
#define C_  512
#define CI_ 256
#define N_  4096
#define EPS_ 1e-5f
#define ZSCALE 64.0f
#define SLICES 16

// ------------------------- device scratch (no allocs) -------------------------
__device__ float vT_buf[B_ * N_ * C_];                 // 32 MB [B,N,C]
__device__ float th_buf[B_ * N_ * CI_];                // 16 MB [B,N,Ci]
__device__ float pg_buf[B_ * 2 * CI_ * N_];            // 32 MB [B, (ph|g), N]
__device__ float y_buf [B_ * N_ * CI_];                // 16 MB [B,N,Ci]
__device__ float Wy_buf[B_ * C_ * N_];                 // 32 MB [B,C,N]
__device__ float Zpart_buf[B_ * SLICES * CI_ * CI_];   // 16 MB
__device__ float Zt_buf[B_ * CI_ * CI_];               //  1 MB
__device__ float Wpg_buf[2 * CI_ * C_];                //  1 MB concat weights
__device__ float bpg_buf[2 * CI_];
__device__ float bn_mean[C_];
__device__ float bn_rstd[C_];

// ------------------------------- GEMM config ----------------------------------
#define PITCH 40                        // halves per smem row (80B) -> conflict-free
#define TILE_HALVES (128 * PITCH)       // 5120 halves
#define TILE_BYTES  (TILE_HALVES * 2)   // 10240 B
#define BUF_BYTES   (4 * TILE_BYTES)    // Ah, Al, Bh, Bl = 40960
#define SMEM_GEMM_BYTES (2 * BUF_BYTES + 1024)

__device__ __forceinline__ uint32_t smem_u32(const void* p) {
    uint32_t a;
    asm("{ .reg .u64 t; cvta.to.shared.u64 t, %1; cvt.u32.u64 %0, t; }" : "=r"(a) : "l"(p));
    return a;
}
__device__ __forceinline__ void ldm_x4(uint32_t* r, uint32_t addr) {
    asm volatile("ldmatrix.sync.aligned.m8n8.x4.shared.b16 {%0,%1,%2,%3}, [%4];"
                 : "=r"(r[0]), "=r"(r[1]), "=r"(r[2]), "=r"(r[3]) : "r"(addr));
}
__device__ __forceinline__ void mma16816(float* c, const uint32_t* a, const uint32_t* b) {
    asm volatile(
        "mma.sync.aligned.m16n8k16.row.col.f32.f16.f16.f32 "
        "{%0,%1,%2,%3}, {%4,%5,%6,%7}, {%8,%9}, {%0,%1,%2,%3};"
        : "+f"(c[0]), "+f"(c[1]), "+f"(c[2]), "+f"(c[3])
        : "r"(a[0]), "r"(a[1]), "r"(a[2]), "r"(a[3]), "r"(b[0]), "r"(b[1]));
}

// split fp32x4 -> hi/lo fp16 pairs, store to smem (lo at +TILE_HALVES)
__device__ __forceinline__ void split_store(half* base, int idx, float4 x) {
    half2 h01 = __floats2half2_rn(x.x, x.y);
    half2 h23 = __floats2half2_rn(x.z, x.w);
    float2 f01 = __half22float2(h01);
    float2 f23 = __half22float2(h23);
    half2 l01 = __floats2half2_rn(x.x - f01.x, x.y - f01.y);
    half2 l23 = __floats2half2_rn(x.z - f23.x, x.w - f23.y);
    *(half2*)&base[idx]     = h01;
    *(half2*)&base[idx + 2] = h23;
    *(half2*)&base[TILE_HALVES + idx]     = l01;
    *(half2*)&base[TILE_HALVES + idx + 2] = l23;
}

// ------------------------------------------------------------------------------
// D[M,Nt] = alpha * A[M,K] @ B[Nt,K]^T + biasM[row] + biasN[col]
// A, B row-major, row strides ldA/ldB (K contiguous). 128x128x32 tiles, 256 thr.
// grid = (Nt/128, M/128, nBatch*nSlices); per-z: X += b*sbX + s*slX.
// fp16x3 (hh + lh + hl), fp32 accumulate.
// ------------------------------------------------------------------------------
__global__ __launch_bounds__(256, 1)
void gemm_fp16x3(const float* __restrict__ A, const float* __restrict__ Bm,
                 float* __restrict__ D,
                 const float* __restrict__ biasM, const float* __restrict__ biasN,
                 int M, int Nt, int K, int ldA, int ldB, float alpha,
                 int nSlices,
                 long sbA, long slA, long sbB, long slB, long sbD, long slD)
{
    extern __shared__ char smem[];
    half*  sh  = (half*)smem;
    float* sBM = (float*)(smem + 2 * BUF_BYTES);
    float* sBN = sBM + 128;
    const uint32_t sbu = smem_u32(sh);

    const int tid = threadIdx.x;
    const int bx = blockIdx.x, by = blockIdx.y, bz = blockIdx.z;
    const int bb = bz / nSlices;
    const int ss = bz % nSlices;
    A  += bb * sbA + ss * slA + (long)(by * 128) * ldA;
    Bm += bb * sbB + ss * slB + (long)(bx * 128) * ldB;
    D  += bb * sbD + ss * slD;

    if (tid < 128) {
        sBM[tid] = biasM ? biasM[by * 128 + tid] : 0.f;
        sBN[tid] = biasN ? biasN[bx * 128 + tid] : 0.f;
    }

    const int sf = tid & 7;       // k-chunk (4 floats)
    const int sr = tid >> 3;      // 0..31 (row base)
    const int nIter = K / 32;

    // incremental global pointers (4 rows each for A and B)
    const float* pA[4];
    const float* pB[4];
#pragma unroll
    for (int i = 0; i < 4; ++i) {
        pA[i] = A  + (long)(sr + 32 * i) * ldA + sf * 4;
        pB[i] = Bm + (long)(sr + 32 * i) * ldB + sf * 4;
    }

    float4 ra[4], rb[4];
#pragma unroll
    for (int i = 0; i < 4; ++i) {
        ra[i] = *(const float4*)pA[i]; pA[i] += 32;
        rb[i] = *(const float4*)pB[i]; pB[i] += 32;
    }
    {
        half* Ab = sh;                       // buf 0
        half* Bb = sh + 2 * TILE_HALVES;
#pragma unroll
        for (int i = 0; i < 4; ++i) {
            const int idx = (sr + 32 * i) * PITCH + sf * 4;
            split_store(Ab, idx, ra[i]);
            split_store(Bb, idx, rb[i]);
        }
    }
    __syncthreads();

    float acc[4][4][4];
#pragma unroll
    for (int mi = 0; mi < 4; ++mi)
#pragma unroll
        for (int ni = 0; ni < 4; ++ni)
#pragma unroll
            for (int q = 0; q < 4; ++q) acc[mi][ni][q] = 0.f;

    const int wid = tid >> 5, lid = tid & 31;
    const int wm = (wid >> 2) * 64;   // warp m offset (0/64)
    const int wn = (wid & 3) * 32;    // warp n offset
    const int g = lid >> 2;           // group id 0..7
    const int t = lid & 3;            // thread in group

    // ldmatrix lane offsets (bytes)
    // A x4 quadrants: (m0-7,k0-7),(m8-15,k0-7),(m0-7,k8-15),(m8-15,k8-15)
    const uint32_t laneA = (uint32_t)((lid & 15) * (PITCH * 2) + (lid >> 4) * 16);
    // B x4 quadrants: (n0-7,k0-7),(n0-7,k8-15),(n8-15,k0-7),(n8-15,k8-15)
    const uint32_t laneB = (uint32_t)((((lid >> 4) * 8) + (lid & 7)) * (PITCH * 2)
                                      + ((lid >> 3) & 1) * 16);
    const uint32_t aWarp = sbu + (uint32_t)(wm * (PITCH * 2)) + laneA;             // A hi region
    const uint32_t bWarp = sbu + 2 * TILE_BYTES + (uint32_t)(wn * (PITCH * 2)) + laneB;

    for (int it = 0; it < nIter; ++it) {
        const int buf = it & 1;
        const bool hasNext = (it + 1 < nIter);
        if (hasNext) {
#pragma unroll
            for (int i = 0; i < 4; ++i) {
                ra[i] = *(const float4*)pA[i]; pA[i] += 32;
                rb[i] = *(const float4*)pB[i]; pB[i] += 32;
            }
        }

        const uint32_t bo = (uint32_t)(buf * BUF_BYTES);
#pragma unroll
        for (int kk = 0; kk < 2; ++kk) {
            const uint32_t ko = (uint32_t)(kk * 32);   // 16 halves
            uint32_t ah[4][4], al[4][4];
#pragma unroll
            for (int mi = 0; mi < 4; ++mi) {
                const uint32_t addr = aWarp + bo + (uint32_t)(mi * 16 * PITCH * 2) + ko;
                ldm_x4(ah[mi], addr);
                ldm_x4(al[mi], addr + TILE_BYTES);
            }
            uint32_t bh[2][4], bl[2][4];
#pragma unroll
            for (int nb = 0; nb < 2; ++nb) {
                const uint32_t addr = bWarp + bo + (uint32_t)(nb * 16 * PITCH * 2) + ko;
                ldm_x4(bh[nb], addr);
                ldm_x4(bl[nb], addr + TILE_BYTES);
            }
#pragma unroll
            for (int mi = 0; mi < 4; ++mi)
#pragma unroll
                for (int ni = 0; ni < 4; ++ni) {
                    const uint32_t* bb  = &bh[ni >> 1][(ni & 1) * 2];
                    const uint32_t* bbl = &bl[ni >> 1][(ni & 1) * 2];
                    mma16816(acc[mi][ni], ah[mi], bb);
                    mma16816(acc[mi][ni], al[mi], bb);
                    mma16816(acc[mi][ni], ah[mi], bbl);
                }
        }

        if (hasNext) {
            half* Ab = sh + (buf ^ 1) * (BUF_BYTES / 2);   // halves offset
            half* Bb = Ab + 2 * TILE_HALVES;
#pragma unroll
            for (int i = 0; i < 4; ++i) {
                const int idx = (sr + 32 * i) * PITCH + sf * 4;
                split_store(Ab, idx, ra[i]);
                split_store(Bb, idx, rb[i]);
            }
        }
        __syncthreads();
    }

    // epilogue
#pragma unroll
    for (int mi = 0; mi < 4; ++mi) {
        const int row0 = wm + mi * 16 + g;
        const float bm0 = sBM[row0], bm1 = sBM[row0 + 8];
        const long gr0 = (long)(by * 128 + row0) * Nt + bx * 128;
        const long gr1 = gr0 + 8L * Nt;
#pragma unroll
        for (int ni = 0; ni < 4; ++ni) {
            const int col = wn + ni * 8 + t * 2;
            const float bn0 = sBN[col], bn1 = sBN[col + 1];
            float2 o0, o1;
            o0.x = alpha * acc[mi][ni][0] + bm0 + bn0;
            o0.y = alpha * acc[mi][ni][1] + bm0 + bn1;
            o1.x = alpha * acc[mi][ni][2] + bm1 + bn0;
            o1.y = alpha * acc[mi][ni][3] + bm1 + bn1;
            *(float2*)&D[gr0 + col] = o0;
            *(float2*)&D[gr1 + col] = o1;
        }
    }
}

// ------------------------------------------------------------------------------
// v [B,C,N] -> vT [B,N,C]
__global__ __launch_bounds__(256)
void transpose_kernel(const float* __restrict__ v, float* __restrict__ o)
{
    __shared__ float t[32][33];
    const int b = blockIdx.z;
    const int n0 = blockIdx.x * 32, c0 = blockIdx.y * 32;
    const int tx = threadIdx.x, ty = threadIdx.y;   // 32 x 8
#pragma unroll
    for (int i = 0; i < 4; ++i)
        t[ty + 8 * i][tx] = v[((long)b * C_ + c0 + ty + 8 * i) * N_ + n0 + tx];
    __syncthreads();
#pragma unroll
    for (int i = 0; i < 4; ++i)
        o[((long)b * N_ + n0 + ty + 8 * i) * C_ + c0 + tx] = t[tx][ty + 8 * i];
}

// concat [Wph; Wg] -> Wpg [2Ci, C], [bph; bg] -> bpg
__global__ __launch_bounds__(256)
void concat_pg_kernel(const float* __restrict__ Wph, const float* __restrict__ bph,
                      const float* __restrict__ Wg,  const float* __restrict__ bg,
                      float* __restrict__ W, float* __restrict__ b)
{
    const int i = blockIdx.x * 256 + threadIdx.x;    // float4 index, 131072 total
    const int half4 = CI_ * C_ / 4;
    float4 val = (i < half4) ? ((const float4*)Wph)[i] : ((const float4*)Wg)[i - half4];
    ((float4*)W)[i] = val;
    if (i < CI_) b[i] = bph[i];
    else if (i < 2 * CI_) b[i] = bg[i - CI_];
}

// ------------------------------------------------------------------------------
// reduce split-K partials: Zt[b][i] = sum_s Zpart[(b*SLICES+s)][i]
__global__ __launch_bounds__(256)
void zreduce_kernel(const float* __restrict__ part, float* __restrict__ out)
{
    const int i = blockIdx.x * 256 + threadIdx.x;
    const int b = blockIdx.y;
    const float* p = part + (long)b * SLICES * (CI_ * CI_) + i;
    float s = 0.f;
#pragma unroll
    for (int k = 0; k < SLICES; ++k) s += p[(long)k * (CI_ * CI_)];
    out[(long)b * (CI_ * CI_) + i] = s;
}

// ------------------------------------------------------------------------------
__global__ __launch_bounds__(256)
void bn_stats_kernel(const float* __restrict__ Wy)
{
    const int c = blockIdx.x;
    float s = 0.f, ss = 0.f;
    for (int i = threadIdx.x; i < B_ * N_; i += 256) {
        const int b = i >> 12;
        const int n = i & (N_ - 1);
        const float x = Wy[((long)b * C_ + c) * N_ + n];
        s += x;
        ss += x * x;
    }
    __shared__ float sh_s[256], sh_q[256];
    sh_s[threadIdx.x] = s;
    sh_q[threadIdx.x] = ss;
    __syncthreads();
    for (int o = 128; o > 0; o >>= 1) {
        if (threadIdx.x < o) {
            sh_s[threadIdx.x] += sh_s[threadIdx.x + o];
            sh_q[threadIdx.x] += sh_q[threadIdx.x + o];
        }
        __syncthreads();
    }
    if (threadIdx.x == 0) {
        const float inv = 1.f / (float)(B_ * N_);
        const float m   = sh_s[0] * inv;
        const float var = fmaxf(sh_q[0] * inv - m * m, 0.f);
        bn_mean[c] = m;
        bn_rstd[c] = rsqrtf(var + EPS_);
    }
}

__global__ __launch_bounds__(256)
void bn_apply_kernel(const float* __restrict__ Wy,
                     const float* __restrict__ v,
                     const float* __restrict__ gamma,
                     const float* __restrict__ beta,
                     float* __restrict__ out)
{
    const long idx = (long)blockIdx.x * 256 + threadIdx.x;
    const long total4 = (long)B_ * C_ * N_ / 4;
    if (idx >= total4) return;
    const int c = (int)((idx * 4 / N_) % C_);
    const float sc = bn_rstd[c] * gamma[c];
    const float sh = beta[c] - bn_mean[c] * sc;
    const float4 w  = ((const float4*)Wy)[idx];
    const float4 vv = ((const float4*)v)[idx];
    float4 o;
    o.x = w.x * sc + sh + vv.x;
    o.y = w.y * sc + sh + vv.y;
    o.z = w.z * sc + sh + vv.z;
    o.w = w.w * sc + sh + vv.w;
    ((float4*)out)[idx] = o;
}

// ------------------------------------------------------------------------------
#define SYM(p, s) cudaGetSymbolAddress((void**)&p, s)

extern "C" void kernel_launch(void* const* d_in, const int* in_sizes, int n_in,
                              void* d_out, int out_size)
{
    const float* v     = (const float*)d_in[0];
    const float* Wg    = (const float*)d_in[1];
    const float* bg    = (const float*)d_in[2];
    const float* Wth   = (const float*)d_in[3];
    const float* bth   = (const float*)d_in[4];
    const float* Wph   = (const float*)d_in[5];
    const float* bph   = (const float*)d_in[6];
    const float* Ww    = (const float*)d_in[7];
    const float* bw    = (const float*)d_in[8];
    const float* gamma = (const float*)d_in[9];
    const float* beta  = (const float*)d_in[10];
    float* out = (float*)d_out;

    float *vT, *th, *pg, *y, *Wy, *Zp, *Zt, *Wpg, *bpg;
    SYM(vT, vT_buf);
    SYM(th, th_buf);
    SYM(pg, pg_buf);
    SYM(y,  y_buf);
    SYM(Wy, Wy_buf);
    SYM(Zp, Zpart_buf);
    SYM(Zt, Zt_buf);
    SYM(Wpg, Wpg_buf);
    SYM(bpg, bpg_buf);

    cudaFuncSetAttribute(gemm_fp16x3, cudaFuncAttributeMaxDynamicSharedMemorySize, SMEM_GEMM_BYTES);

    const long sVT = (long)N_ * C_;        // vT batch stride
    const long sNC = (long)N_ * CI_;       // [N,Ci]
    const long sPG = (long)2 * CI_ * N_;   // [2Ci,N]
    const long sC  = (long)C_ * N_;        // [C,N]
    const long sZ  = (long)CI_ * CI_;      // 65536

    // 0) v -> vT; weight concat
    transpose_kernel<<<dim3(N_ / 32, C_ / 32, B_), dim3(32, 8)>>>(v, vT);
    concat_pg_kernel<<<(2 * CI_ * C_ / 4) / 256, 256>>>(Wph, bph, Wg, bg, Wpg, bpg);

    // 1) pg[{ph|g}, n] = Wpg . vT + bpg   (fused ph+g projection; biasM)
    gemm_fp16x3<<<dim3(N_ / 128, (2 * CI_) / 128, B_), 256, SMEM_GEMM_BYTES>>>(
        Wpg, vT, pg, bpg, nullptr, 2 * CI_, N_, C_, C_, C_, 1.f,
        1, 0, 0, sVT, 0, sPG, 0);
    // 2) Zpart[z][cg,cth] = (ZSCALE/N) * sum_{m in slice} g[cg,m] ph[cth,m]
    gemm_fp16x3<<<dim3(CI_ / 128, CI_ / 128, B_ * SLICES), 256, SMEM_GEMM_BYTES>>>(
        pg + (long)CI_ * N_, pg, Zp, nullptr, nullptr,
        CI_, CI_, N_ / SLICES, N_, N_, ZSCALE / (float)N_,
        SLICES, sPG, N_ / SLICES, sPG, N_ / SLICES, SLICES * sZ, sZ);
    // 3) Zt = sum_s Zpart
    zreduce_kernel<<<dim3(sZ / 256, B_), 256>>>(Zp, Zt);
    // 4) th[n,cth] = vT[n,:].Wth[cth,:] + bth   (biasN)
    gemm_fp16x3<<<dim3(CI_ / 128, N_ / 128, B_), 256, SMEM_GEMM_BYTES>>>(
        vT, Wth, th, nullptr, bth, N_, CI_, C_, C_, C_, 1.f,
        1, sVT, 0, 0, 0, sNC, 0);
    // 5) y[n,cg] = (1/ZSCALE) * th[n,:].Zt[cg,:]
    gemm_fp16x3<<<dim3(CI_ / 128, N_ / 128, B_), 256, SMEM_GEMM_BYTES>>>(
        th, Zt, y, nullptr, nullptr, N_, CI_, CI_, CI_, CI_, 1.f / ZSCALE,
        1, sNC, 0, sZ, 0, sNC, 0);
    // 6) Wy[c,n] = Ww[c,:].y[n,:] + bw          (biasM)
    gemm_fp16x3<<<dim3(N_ / 128, C_ / 128, B_), 256, SMEM_GEMM_BYTES>>>(
        Ww, y, Wy, bw, nullptr, C_, N_, CI_, CI_, CI_, 1.f,
        1, 0, 0, sNC, 0, sC, 0);

    // 7) BN stats + apply + residual
    bn_stats_kernel<<<C_, 256>>>(Wy);
    const long total4 = (long)B_ * C_ * N_ / 4;
    bn_apply_kernel<<<(int)((total4 + 255) / 256), 256>>>(Wy, v, gamma, beta, out);
}